// round 1
// baseline (speedup 1.0000x reference)
#include <cuda_runtime.h>
#include <math.h>

// Problem shapes (fixed by reference): x1 [4096,1024], x2 [4096,1024], W* [1024,1024]
constexpr int DIM = 1024;
constexpr int N1  = 4096;
constexpr int N2  = 4096;

// Scratch (alloc-free rule: __device__ globals)
__device__ float g_Q[(size_t)N1 * DIM];
__device__ float g_K[(size_t)N2 * DIM];
__device__ float g_V[(size_t)N2 * DIM];
__device__ float g_S[(size_t)N1 * N2];

// ---------------------------------------------------------------------------
// Register-blocked fp32 GEMM.
//   TRANSB = true  : C[M,N] = A[M,K] * B[N,K]^T   (B row-major [N,K])
//   TRANSB = false : C[M,N] = A[M,K] * B[K,N]     (B row-major [K,N])
// Tiles: BM=BN=64, BK=16, 256 threads, 4x4 accumulators per thread.
// Assumes M,N multiples of 64 and K multiple of 16 (true for all calls here).
// ---------------------------------------------------------------------------
template <bool TRANSB>
__global__ __launch_bounds__(256) void sgemm64(const float* __restrict__ A,
                                               const float* __restrict__ B,
                                               float* __restrict__ C,
                                               int M, int N, int K) {
    constexpr int BM = 64, BN = 64, BK = 16;
    __shared__ __align__(16) float As[BK][BM];
    __shared__ __align__(16) float Bs[BK][BN];

    const int tid = threadIdx.x;
    const int m0 = blockIdx.y * BM;
    const int n0 = blockIdx.x * BN;

    const int ty = tid >> 4;        // 0..15
    const int tx = tid & 15;        // 0..15

    // A-load (and TRANSB B-load) mapping: 64 rows x 16 cols, one float4 per thread
    const int lrow  = tid >> 2;       // 0..63
    const int lcol4 = (tid & 3) * 4;  // 0,4,8,12
    // !TRANSB B-load mapping: 16 rows x 64 cols, one float4 per thread
    const int brow  = tid >> 4;       // 0..15
    const int bcol4 = (tid & 15) * 4; // 0..60

    float acc[4][4] = {};

    for (int k0 = 0; k0 < K; k0 += BK) {
        // Load A tile (transpose into As[k][m])
        float4 av = *reinterpret_cast<const float4*>(
            &A[(size_t)(m0 + lrow) * K + (k0 + lcol4)]);
        As[lcol4 + 0][lrow] = av.x;
        As[lcol4 + 1][lrow] = av.y;
        As[lcol4 + 2][lrow] = av.z;
        As[lcol4 + 3][lrow] = av.w;

        if (TRANSB) {
            // B is [N,K] row-major; want Bs[k][n] = B[n][k]
            float4 bv = *reinterpret_cast<const float4*>(
                &B[(size_t)(n0 + lrow) * K + (k0 + lcol4)]);
            Bs[lcol4 + 0][lrow] = bv.x;
            Bs[lcol4 + 1][lrow] = bv.y;
            Bs[lcol4 + 2][lrow] = bv.z;
            Bs[lcol4 + 3][lrow] = bv.w;
        } else {
            // B is [K,N] row-major; Bs[k][n] = B[k][n], vector store
            float4 bv = *reinterpret_cast<const float4*>(
                &B[(size_t)(k0 + brow) * N + (n0 + bcol4)]);
            *reinterpret_cast<float4*>(&Bs[brow][bcol4]) = bv;
        }
        __syncthreads();

#pragma unroll
        for (int kk = 0; kk < BK; kk++) {
            float4 ra = *reinterpret_cast<const float4*>(&As[kk][ty * 4]);
            float4 rb = *reinterpret_cast<const float4*>(&Bs[kk][tx * 4]);
            float a[4] = {ra.x, ra.y, ra.z, ra.w};
            float b[4] = {rb.x, rb.y, rb.z, rb.w};
#pragma unroll
            for (int i = 0; i < 4; i++)
#pragma unroll
                for (int j = 0; j < 4; j++)
                    acc[i][j] = fmaf(a[i], b[j], acc[i][j]);
        }
        __syncthreads();
    }

#pragma unroll
    for (int i = 0; i < 4; i++) {
        float4 v = make_float4(acc[i][0], acc[i][1], acc[i][2], acc[i][3]);
        *reinterpret_cast<float4*>(
            &C[(size_t)(m0 + ty * 4 + i) * N + (n0 + tx * 4)]) = v;
    }
}

// ---------------------------------------------------------------------------
// Row softmax over S [rows, 4096], in place. One block per row; 256 threads;
// 16 elements per thread kept in registers across max / exp-sum / scale.
// ---------------------------------------------------------------------------
__global__ __launch_bounds__(256) void softmax4096(float* __restrict__ S) {
    constexpr int N = 4096;
    float* row = S + (size_t)blockIdx.x * N;
    const int t = threadIdx.x;

    float4 v[4];
#pragma unroll
    for (int c = 0; c < 4; c++)
        v[c] = *reinterpret_cast<const float4*>(&row[t * 4 + c * 1024]);

    // --- max ---
    float m = -INFINITY;
#pragma unroll
    for (int c = 0; c < 4; c++)
        m = fmaxf(m, fmaxf(fmaxf(v[c].x, v[c].y), fmaxf(v[c].z, v[c].w)));

    __shared__ float red[8];
#pragma unroll
    for (int o = 16; o > 0; o >>= 1)
        m = fmaxf(m, __shfl_xor_sync(0xffffffffu, m, o));
    if ((t & 31) == 0) red[t >> 5] = m;
    __syncthreads();
    if (t < 8) {
        m = red[t];
#pragma unroll
        for (int o = 4; o > 0; o >>= 1)
            m = fmaxf(m, __shfl_xor_sync(0xffu, m, o));
        if (t == 0) red[0] = m;
    }
    __syncthreads();
    const float rmax = red[0];
    __syncthreads();

    // --- exp + sum ---
    float s = 0.f;
#pragma unroll
    for (int c = 0; c < 4; c++) {
        v[c].x = __expf(v[c].x - rmax);
        v[c].y = __expf(v[c].y - rmax);
        v[c].z = __expf(v[c].z - rmax);
        v[c].w = __expf(v[c].w - rmax);
        s += (v[c].x + v[c].y) + (v[c].z + v[c].w);
    }
#pragma unroll
    for (int o = 16; o > 0; o >>= 1)
        s += __shfl_xor_sync(0xffffffffu, s, o);
    if ((t & 31) == 0) red[t >> 5] = s;
    __syncthreads();
    if (t < 8) {
        s = red[t];
#pragma unroll
        for (int o = 4; o > 0; o >>= 1)
            s += __shfl_xor_sync(0xffu, s, o);
        if (t == 0) red[0] = s;
    }
    __syncthreads();
    const float inv = 1.0f / red[0];

    // --- scale + store ---
#pragma unroll
    for (int c = 0; c < 4; c++) {
        v[c].x *= inv; v[c].y *= inv; v[c].z *= inv; v[c].w *= inv;
        *reinterpret_cast<float4*>(&row[t * 4 + c * 1024]) = v[c];
    }
}

extern "C" void kernel_launch(void* const* d_in, const int* in_sizes, int n_in,
                              void* d_out, int out_size) {
    const float* x1 = (const float*)d_in[0];
    const float* x2 = (const float*)d_in[1];
    const float* Wq = (const float*)d_in[2];
    const float* Wk = (const float*)d_in[3];
    const float* Wv = (const float*)d_in[4];
    float* out = (float*)d_out;

    float *Q, *K, *V, *S;
    cudaGetSymbolAddress((void**)&Q, g_Q);
    cudaGetSymbolAddress((void**)&K, g_K);
    cudaGetSymbolAddress((void**)&V, g_V);
    cudaGetSymbolAddress((void**)&S, g_S);

    dim3 blk(256);
    // Projections: [4096,1024] = [4096,1024] x [1024,1024]^T
    dim3 gProj(DIM / 64, N1 / 64);
    sgemm64<true><<<gProj, blk>>>(x1, Wq, Q, N1, DIM, DIM);
    sgemm64<true><<<gProj, blk>>>(x2, Wk, K, N2, DIM, DIM);
    sgemm64<true><<<gProj, blk>>>(x2, Wv, V, N2, DIM, DIM);

    // Scores: [4096,4096] = Q x K^T
    dim3 gS(N2 / 64, N1 / 64);
    sgemm64<true><<<gS, blk>>>(Q, K, S, N1, N2, DIM);

    // Softmax rows
    softmax4096<<<N1, blk>>>(S);

    // Output: [4096,1024] = P x V
    dim3 gO(DIM / 64, N1 / 64);
    sgemm64<false><<<gO, blk>>>(S, V, out, N1, DIM, N2);
}

// round 3
// speedup vs baseline: 3.7981x; 3.7981x over previous
#include <cuda_runtime.h>
#include <cuda_bf16.h>
#include <cstdint>
#include <math.h>

// Shapes fixed by the reference
constexpr int DIM = 1024;
constexpr int N1  = 4096;
constexpr int N2  = 4096;

// ---------------- scratch (__device__ globals: alloc-free rule) ----------------
__device__ __nv_bfloat16 g_x1h[(size_t)N1 * DIM], g_x1l[(size_t)N1 * DIM];
__device__ __nv_bfloat16 g_x2h[(size_t)N2 * DIM], g_x2l[(size_t)N2 * DIM];
__device__ __nv_bfloat16 g_Wqh[(size_t)DIM * DIM], g_Wql[(size_t)DIM * DIM];
__device__ __nv_bfloat16 g_Wkh[(size_t)DIM * DIM], g_Wkl[(size_t)DIM * DIM];
__device__ __nv_bfloat16 g_Wvh[(size_t)DIM * DIM], g_Wvl[(size_t)DIM * DIM];
__device__ __nv_bfloat16 g_Qh[(size_t)N1 * DIM],  g_Ql[(size_t)N1 * DIM];
__device__ __nv_bfloat16 g_Kh[(size_t)N2 * DIM],  g_Kl[(size_t)N2 * DIM];
__device__ float         g_Vf[(size_t)N2 * DIM];
__device__ __nv_bfloat16 g_Vth[(size_t)DIM * N2], g_Vtl[(size_t)DIM * N2];
__device__ float         g_S[(size_t)N1 * N2];
__device__ __nv_bfloat16 g_Ph[(size_t)N1 * N2],   g_Pl[(size_t)N1 * N2];

// ---------------- helpers ----------------
__device__ __forceinline__ uint32_t smem_u32(const void* p) {
    uint32_t a;
    asm("{ .reg .u64 t; cvta.to.shared.u64 t, %1; cvt.u32.u64 %0, t; }" : "=r"(a) : "l"(p));
    return a;
}
__device__ __forceinline__ void cp_async16(uint32_t dst, const void* src) {
    asm volatile("cp.async.cg.shared.global [%0], [%1], 16;" :: "r"(dst), "l"(src));
}
#define CP_COMMIT() asm volatile("cp.async.commit_group;" ::: "memory")
#define CP_WAIT0()  asm volatile("cp.async.wait_group 0;" ::: "memory")

__device__ __forceinline__ void ldsm_x4(uint32_t* r, uint32_t addr) {
    asm volatile("ldmatrix.sync.aligned.m8n8.x4.shared.b16 {%0,%1,%2,%3}, [%4];"
        : "=r"(r[0]), "=r"(r[1]), "=r"(r[2]), "=r"(r[3]) : "r"(addr));
}
__device__ __forceinline__ void mma16816(float* d, const uint32_t* a, const uint32_t* b) {
    asm volatile("mma.sync.aligned.m16n8k16.row.col.f32.bf16.bf16.f32 "
        "{%0,%1,%2,%3}, {%4,%5,%6,%7}, {%8,%9}, {%0,%1,%2,%3};"
        : "+f"(d[0]), "+f"(d[1]), "+f"(d[2]), "+f"(d[3])
        : "r"(a[0]), "r"(a[1]), "r"(a[2]), "r"(a[3]), "r"(b[0]), "r"(b[1]));
}
__device__ __forceinline__ void split_f32(float v, __nv_bfloat16& h, __nv_bfloat16& l) {
    h = __float2bfloat16(v);
    l = __float2bfloat16(v - __bfloat162float(h));
}

// ---------------- HMMA GEMM: C[M,N] = (Ah+Al) * (Bh+Bl)^T (3-product split) ----------------
// A: [M,K] bf16 K-major hi/lo; B: [N,K] bf16 K-major hi/lo. BM=BN=128, BK=64.
// EPI 0: fp32 C. EPI 1: C split into hi/lo bf16.
constexpr int BM = 128, BN = 128, BK = 64;
constexpr int TILE_B  = 128 * 128;        // one operand tile: 128 rows x 128B (BK=64 bf16)
constexpr int STAGE_B = 4 * TILE_B;       // Ah, Al, Bh, Bl = 64KB
constexpr int GEMM_SMEM = 2 * STAGE_B;    // 128KB double buffer

template <int EPI>
__global__ void __launch_bounds__(256, 1)
gemm_mma(const __nv_bfloat16* __restrict__ Ah, const __nv_bfloat16* __restrict__ Al,
         const __nv_bfloat16* __restrict__ Bh, const __nv_bfloat16* __restrict__ Bl,
         float* __restrict__ Cf, __nv_bfloat16* __restrict__ Ch, __nv_bfloat16* __restrict__ Cl,
         int Kdim, int ldc) {
    extern __shared__ __align__(1024) char sm[];
    const uint32_t sbase = smem_u32(sm);
    const int tid  = threadIdx.x;
    const int wid  = tid >> 5;
    const int lane = tid & 31;
    const int m0 = blockIdx.y * BM;
    const int n0 = blockIdx.x * BN;
    // 8 warps: 4 along m, 2 along n. Warp tile 32(m) x 64(n).
    const int wm = (wid & 3) * 32;
    const int wn = (wid >> 2) * 64;

    const __nv_bfloat16* srcs[4] = {Ah, Al, Bh, Bl};
    const int rb[4] = {m0, m0, n0, n0};

    // Load one BK chunk (4 tiles of 128x128B) with cp.async + XOR swizzle.
    auto load_chunk = [&](int k0, int s) {
#pragma unroll
        for (int t = 0; t < 4; t++) {
            const __nv_bfloat16* src = srcs[t] + (size_t)rb[t] * Kdim + k0;
            const uint32_t dst0 = sbase + s * STAGE_B + t * TILE_B;
#pragma unroll
            for (int it = 0; it < 4; it++) {
                int idx = tid + it * 256;          // 0..1023
                int row = idx >> 3;                // 0..127
                int ch  = idx & 7;                 // 16B chunk within 128B row
                uint32_t off = (uint32_t)(row << 7) | (uint32_t)((ch ^ (row & 7)) << 4);
                cp_async16(dst0 + off, (const char*)(src + (size_t)row * Kdim) + ch * 16);
            }
        }
    };

    // ldmatrix lane mappings
    const int arow = lane & 15;           // m row within 16
    const int akh  = lane >> 4;           // k half (0/1 -> 16B)
    const int brow = (lane & 7) + ((lane >> 4) << 3);   // n row within 16
    const int bkh  = (lane >> 3) & 1;                   // k half

    float acc[2][8][4];
#pragma unroll
    for (int a = 0; a < 2; a++)
#pragma unroll
        for (int b = 0; b < 8; b++)
#pragma unroll
            for (int r = 0; r < 4; r++) acc[a][b][r] = 0.f;

    const int NC = Kdim / BK;
    load_chunk(0, 0);
    CP_COMMIT();
    CP_WAIT0();
    __syncthreads();

    for (int c = 0; c < NC; c++) {
        const int s = c & 1;
        if (c + 1 < NC) { load_chunk((c + 1) * BK, s ^ 1); CP_COMMIT(); }
        const uint32_t st = sbase + s * STAGE_B;

#pragma unroll
        for (int ks = 0; ks < 4; ks++) {
            uint32_t aH[2][4], aL[2][4];
#pragma unroll
            for (int mt = 0; mt < 2; mt++) {
                uint32_t ro  = (uint32_t)(wm + mt * 16 + arow) << 7;
                uint32_t col = (uint32_t)(((ks * 2 + akh) ^ (arow & 7)) << 4);
                ldsm_x4(aH[mt], st + ro + col);
                ldsm_x4(aL[mt], st + TILE_B + ro + col);
            }
            uint32_t bH[4][4], bL[4][4];
#pragma unroll
            for (int nt = 0; nt < 4; nt++) {
                uint32_t ro  = (uint32_t)(wn + nt * 16 + brow) << 7;
                uint32_t col = (uint32_t)(((ks * 2 + bkh) ^ (brow & 7)) << 4);
                ldsm_x4(bH[nt], st + 2 * TILE_B + ro + col);
                ldsm_x4(bL[nt], st + 3 * TILE_B + ro + col);
            }
#pragma unroll
            for (int mt = 0; mt < 2; mt++)
#pragma unroll
                for (int nt = 0; nt < 4; nt++) {
                    mma16816(acc[mt][nt * 2],     aH[mt], &bH[nt][0]);
                    mma16816(acc[mt][nt * 2 + 1], aH[mt], &bH[nt][2]);
                    mma16816(acc[mt][nt * 2],     aH[mt], &bL[nt][0]);
                    mma16816(acc[mt][nt * 2 + 1], aH[mt], &bL[nt][2]);
                    mma16816(acc[mt][nt * 2],     aL[mt], &bH[nt][0]);
                    mma16816(acc[mt][nt * 2 + 1], aL[mt], &bH[nt][2]);
                }
        }
        if (c + 1 < NC) { CP_WAIT0(); __syncthreads(); }
    }

    // Epilogue. mma frag layout: d0,d1 -> (row=lane/4, col=(lane%4)*2+{0,1}); d2,d3 -> row+8.
    const int erow = lane >> 2;
    const int ecol = (lane & 3) * 2;
#pragma unroll
    for (int mt = 0; mt < 2; mt++)
#pragma unroll
        for (int nf = 0; nf < 8; nf++) {
            const int col = n0 + wn + nf * 8 + ecol;
#pragma unroll
            for (int h = 0; h < 2; h++) {
                const int row = m0 + wm + mt * 16 + erow + h * 8;
                const float v0 = acc[mt][nf][h * 2];
                const float v1 = acc[mt][nf][h * 2 + 1];
                if (EPI == 0) {
                    *reinterpret_cast<float2*>(Cf + (size_t)row * ldc + col) =
                        make_float2(v0, v1);
                } else {
                    __nv_bfloat16 h0, l0, h1, l1;
                    split_f32(v0, h0, l0);
                    split_f32(v1, h1, l1);
                    __nv_bfloat162 hv; hv.x = h0; hv.y = h1;
                    __nv_bfloat162 lv; lv.x = l0; lv.y = l1;
                    *reinterpret_cast<__nv_bfloat162*>(Ch + (size_t)row * ldc + col) = hv;
                    *reinterpret_cast<__nv_bfloat162*>(Cl + (size_t)row * ldc + col) = lv;
                }
            }
        }
}

// ---------------- fp32 -> bf16 hi/lo split (elementwise, float4) ----------------
__global__ void __launch_bounds__(256) split_kernel(const float* __restrict__ src,
                                                    __nv_bfloat16* __restrict__ h,
                                                    __nv_bfloat16* __restrict__ l) {
    const size_t i = ((size_t)blockIdx.x * blockDim.x + threadIdx.x) * 4;
    float4 v = *reinterpret_cast<const float4*>(src + i);
    __nv_bfloat16 h0, l0, h1, l1, h2, l2, h3, l3;
    split_f32(v.x, h0, l0); split_f32(v.y, h1, l1);
    split_f32(v.z, h2, l2); split_f32(v.w, h3, l3);
    __nv_bfloat162 ha; ha.x = h0; ha.y = h1;
    __nv_bfloat162 hb; hb.x = h2; hb.y = h3;
    __nv_bfloat162 la; la.x = l0; la.y = l1;
    __nv_bfloat162 lb; lb.x = l2; lb.y = l3;
    *reinterpret_cast<__nv_bfloat162*>(h + i) = ha;
    *reinterpret_cast<__nv_bfloat162*>(h + i + 2) = hb;
    *reinterpret_cast<__nv_bfloat162*>(l + i) = la;
    *reinterpret_cast<__nv_bfloat162*>(l + i + 2) = lb;
}

// ---------------- V [4096,1024] f32 -> Vt hi/lo bf16 [1024,4096] ----------------
__global__ void __launch_bounds__(256) transpose_split_kernel(const float* __restrict__ V,
                                                              __nv_bfloat16* __restrict__ Vth,
                                                              __nv_bfloat16* __restrict__ Vtl) {
    __shared__ float t[32][33];
    const int bx = blockIdx.x * 32;   // dim (col of V)
    const int by = blockIdx.y * 32;   // seq (row of V)
    const int x = threadIdx.x, y = threadIdx.y;   // 32x8
#pragma unroll
    for (int j = 0; j < 32; j += 8)
        t[y + j][x] = V[(size_t)(by + y + j) * DIM + bx + x];
    __syncthreads();
#pragma unroll
    for (int j = 0; j < 32; j += 8) {
        float v = t[x][y + j];
        __nv_bfloat16 h, l;
        split_f32(v, h, l);
        size_t o = (size_t)(bx + y + j) * N2 + by + x;
        Vth[o] = h;
        Vtl[o] = l;
    }
}

// ---------------- row softmax over S [N1,4096] -> P hi/lo bf16 ----------------
__global__ void __launch_bounds__(256) softmax4096(const float* __restrict__ S,
                                                   __nv_bfloat16* __restrict__ Ph,
                                                   __nv_bfloat16* __restrict__ Pl) {
    constexpr int N = 4096;
    const float* row = S + (size_t)blockIdx.x * N;
    const int t = threadIdx.x;

    float4 v[4];
#pragma unroll
    for (int c = 0; c < 4; c++)
        v[c] = *reinterpret_cast<const float4*>(&row[t * 4 + c * 1024]);

    float m = -INFINITY;
#pragma unroll
    for (int c = 0; c < 4; c++)
        m = fmaxf(m, fmaxf(fmaxf(v[c].x, v[c].y), fmaxf(v[c].z, v[c].w)));

    __shared__ float red[8];
#pragma unroll
    for (int o = 16; o > 0; o >>= 1) m = fmaxf(m, __shfl_xor_sync(0xffffffffu, m, o));
    if ((t & 31) == 0) red[t >> 5] = m;
    __syncthreads();
    if (t < 8) {
        m = red[t];
#pragma unroll
        for (int o = 4; o > 0; o >>= 1) m = fmaxf(m, __shfl_xor_sync(0xffu, m, o));
        if (t == 0) red[0] = m;
    }
    __syncthreads();
    const float rmax = red[0];
    __syncthreads();

    float s = 0.f;
#pragma unroll
    for (int c = 0; c < 4; c++) {
        v[c].x = __expf(v[c].x - rmax); v[c].y = __expf(v[c].y - rmax);
        v[c].z = __expf(v[c].z - rmax); v[c].w = __expf(v[c].w - rmax);
        s += (v[c].x + v[c].y) + (v[c].z + v[c].w);
    }
#pragma unroll
    for (int o = 16; o > 0; o >>= 1) s += __shfl_xor_sync(0xffffffffu, s, o);
    if ((t & 31) == 0) red[t >> 5] = s;
    __syncthreads();
    if (t < 8) {
        s = red[t];
#pragma unroll
        for (int o = 4; o > 0; o >>= 1) s += __shfl_xor_sync(0xffu, s, o);
        if (t == 0) red[0] = s;
    }
    __syncthreads();
    const float inv = 1.0f / red[0];

    size_t rbase = (size_t)blockIdx.x * N;
#pragma unroll
    for (int c = 0; c < 4; c++) {
        int col = t * 4 + c * 1024;
        float w0 = v[c].x * inv, w1 = v[c].y * inv, w2 = v[c].z * inv, w3 = v[c].w * inv;
        __nv_bfloat16 h0, l0, h1, l1, h2, l2, h3, l3;
        split_f32(w0, h0, l0); split_f32(w1, h1, l1);
        split_f32(w2, h2, l2); split_f32(w3, h3, l3);
        __nv_bfloat162 ha; ha.x = h0; ha.y = h1;
        __nv_bfloat162 hb; hb.x = h2; hb.y = h3;
        __nv_bfloat162 la; la.x = l0; la.y = l1;
        __nv_bfloat162 lb; lb.x = l2; lb.y = l3;
        *reinterpret_cast<__nv_bfloat162*>(Ph + rbase + col) = ha;
        *reinterpret_cast<__nv_bfloat162*>(Ph + rbase + col + 2) = hb;
        *reinterpret_cast<__nv_bfloat162*>(Pl + rbase + col) = la;
        *reinterpret_cast<__nv_bfloat162*>(Pl + rbase + col + 2) = lb;
    }
}

// ---------------- host ----------------
extern "C" void kernel_launch(void* const* d_in, const int* in_sizes, int n_in,
                              void* d_out, int out_size) {
    const float* x1 = (const float*)d_in[0];
    const float* x2 = (const float*)d_in[1];
    const float* Wq = (const float*)d_in[2];
    const float* Wk = (const float*)d_in[3];
    const float* Wv = (const float*)d_in[4];
    float* out = (float*)d_out;

    static bool attr_set = false;
    if (!attr_set) {
        cudaFuncSetAttribute(gemm_mma<0>, cudaFuncAttributeMaxDynamicSharedMemorySize, GEMM_SMEM);
        cudaFuncSetAttribute(gemm_mma<1>, cudaFuncAttributeMaxDynamicSharedMemorySize, GEMM_SMEM);
        attr_set = true;
    }

    __nv_bfloat16 *x1h, *x1l, *x2h, *x2l, *Wqh, *Wql, *Wkh, *Wkl, *Wvh, *Wvl;
    __nv_bfloat16 *Qh, *Ql, *Kh, *Kl, *Vth, *Vtl, *Ph, *Pl;
    float *Vf, *S;
    cudaGetSymbolAddress((void**)&x1h, g_x1h); cudaGetSymbolAddress((void**)&x1l, g_x1l);
    cudaGetSymbolAddress((void**)&x2h, g_x2h); cudaGetSymbolAddress((void**)&x2l, g_x2l);
    cudaGetSymbolAddress((void**)&Wqh, g_Wqh); cudaGetSymbolAddress((void**)&Wql, g_Wql);
    cudaGetSymbolAddress((void**)&Wkh, g_Wkh); cudaGetSymbolAddress((void**)&Wkl, g_Wkl);
    cudaGetSymbolAddress((void**)&Wvh, g_Wvh); cudaGetSymbolAddress((void**)&Wvl, g_Wvl);
    cudaGetSymbolAddress((void**)&Qh, g_Qh);   cudaGetSymbolAddress((void**)&Ql, g_Ql);
    cudaGetSymbolAddress((void**)&Kh, g_Kh);   cudaGetSymbolAddress((void**)&Kl, g_Kl);
    cudaGetSymbolAddress((void**)&Vf, g_Vf);
    cudaGetSymbolAddress((void**)&Vth, g_Vth); cudaGetSymbolAddress((void**)&Vtl, g_Vtl);
    cudaGetSymbolAddress((void**)&S, g_S);
    cudaGetSymbolAddress((void**)&Ph, g_Ph);   cudaGetSymbolAddress((void**)&Pl, g_Pl);

    // splits
    split_kernel<<<(N1 * DIM) / 1024, 256>>>(x1, x1h, x1l);
    split_kernel<<<(N2 * DIM) / 1024, 256>>>(x2, x2h, x2l);
    split_kernel<<<(DIM * DIM) / 1024, 256>>>(Wq, Wqh, Wql);
    split_kernel<<<(DIM * DIM) / 1024, 256>>>(Wk, Wkh, Wkl);
    split_kernel<<<(DIM * DIM) / 1024, 256>>>(Wv, Wvh, Wvl);

    // projections: [4096,1024] x [1024,1024]^T
    dim3 gProj(DIM / BN, N1 / BM);
    gemm_mma<1><<<gProj, 256, GEMM_SMEM>>>(x1h, x1l, Wqh, Wql, nullptr, Qh, Ql, DIM, DIM);
    gemm_mma<1><<<gProj, 256, GEMM_SMEM>>>(x2h, x2l, Wkh, Wkl, nullptr, Kh, Kl, DIM, DIM);
    gemm_mma<0><<<gProj, 256, GEMM_SMEM>>>(x2h, x2l, Wvh, Wvl, Vf, nullptr, nullptr, DIM, DIM);

    // V transpose + split
    transpose_split_kernel<<<dim3(DIM / 32, N2 / 32), dim3(32, 8)>>>(Vf, Vth, Vtl);

    // scores: Q x K^T -> S [4096,4096]
    dim3 gS(N2 / BN, N1 / BM);
    gemm_mma<0><<<gS, 256, GEMM_SMEM>>>(Qh, Ql, Kh, Kl, S, nullptr, nullptr, DIM, N2);

    // softmax -> P hi/lo
    softmax4096<<<N1, 256>>>(S, Ph, Pl);

    // out: P [4096,4096] x Vt[1024,4096]^T -> [4096,1024]
    dim3 gO(DIM / BN, N1 / BM);
    gemm_mma<0><<<gO, 256, GEMM_SMEM>>>(Ph, Pl, Vth, Vtl, out, nullptr, nullptr, N2, DIM);
}